// round 6
// baseline (speedup 1.0000x reference)
#include <cuda_runtime.h>

#define DIM    1024
#define NPAIRS 512
#define NLAYER 10

// Fused single kernel.
//
// Math: with base point 0 both Mobius maps are radial scalings
//   log0(x) = atanh(|x|)/|x| x,  exp0(v) = tanh(|v|)/|v| v,
// and the 10-layer butterfly always pairs adjacent elements (2k,2k+1),
// acting as [[a,b],[-b,a]] = complex multiply by (a - ib). So the whole
// stack is one complex constant W_k per pair (512 total), and
// |butterfly(u)|^2 = s1^2 * sum_k |W_k|^2 (x_{2k}^2 + x_{2k+1}^2).
//
// Each CTA recomputes the 512 W_k into smem (cheap, overlapped with the
// front-batched x loads), so there is no precompute kernel and no
// inter-kernel gap. Warp-per-row, 8 rows per CTA, no inter-warp sync for
// the reduction (warp shuffles only).
__global__ void __launch_bounds__(256, 6)
hyper_butterfly_fused(const float* __restrict__ x,
                      const float* __restrict__ params,
                      float* __restrict__ out) {
    __shared__ __align__(16) float2 sW[NPAIRS];   // 4 KB: (Re W_k, Im W_k)

    const int t    = threadIdx.x;
    const int warp = t >> 5;
    const int lane = t & 31;
    const int row  = (blockIdx.x << 3) + warp;

    const float4* __restrict__ xr = reinterpret_cast<const float4*>(x + (size_t)row * DIM);
    float4* __restrict__ orow     = reinterpret_cast<float4*>(out + (size_t)row * DIM);

    // ── Phase 0: front-batch the row loads (MLP=8, in flight during W compute)
    float4 xv[8];
#pragma unroll
    for (int j = 0; j < 8; ++j) xv[j] = xr[lane + 32 * j];

    // ── Phase 1: cooperative W table (each thread does pairs t and t+256).
    // Layer l (bs=2^l) multiplies pair k by (a - ib) with block index k>>(l-1).
#pragma unroll
    for (int h = 0; h < 2; ++h) {
        const int k = t + h * 256;
        float A = 1.0f, B = 0.0f;
        int off = 2 * DIM;                 // layer 0 (bs=1) skipped, eats 2*1024 params
#pragma unroll
        for (int l = 1; l < NLAYER; ++l) {
            const int blk = k >> (l - 1);
            const float2 ab = *reinterpret_cast<const float2*>(params + off + 2 * blk);
            const float nA = A * ab.x + B * ab.y;   // (A+iB)*(a-ib)
            const float nB = B * ab.x - A * ab.y;
            A = nA; B = nB;
            off += 2 * (DIM >> l);
        }
        sW[k] = make_float2(A, B);
    }

    // ||x||^2 partial — no W needed, consumes loads as they land.
    float r0 = 0.0f;
#pragma unroll
    for (int j = 0; j < 8; ++j)
        r0 += xv[j].x * xv[j].x + xv[j].y * xv[j].y
            + xv[j].z * xv[j].z + xv[j].w * xv[j].w;

    __syncthreads();   // sW ready

    // ── Phase 2: ||W.x||^2 partial, |W|^2 recomputed from smem on the fly.
    const float4* __restrict__ sW4 = reinterpret_cast<const float4*>(sW);
    float r1 = 0.0f;
#pragma unroll
    for (int j = 0; j < 8; ++j) {
        const float4 w = sW4[lane + 32 * j];
        const float wz0 = w.x * w.x + w.y * w.y;
        const float wz1 = w.z * w.z + w.w * w.w;
        r1 += wz0 * (xv[j].x * xv[j].x + xv[j].y * xv[j].y)
            + wz1 * (xv[j].z * xv[j].z + xv[j].w * xv[j].w);
    }

    // Warp butterfly reduce both sums; every lane gets the totals.
#pragma unroll
    for (int o = 16; o; o >>= 1) {
        r0 += __shfl_xor_sync(0xffffffffu, r0, o);
        r1 += __shfl_xor_sync(0xffffffffu, r1, o);
    }

    const float n  = sqrtf(r0);
    const float s1 = atanhf(n) / fmaxf(n, 1e-12f);
    const float m  = s1 * sqrtf(r1);
    const float s  = s1 * tanhf(m) / fmaxf(m, 1e-12f);

    // ── Phase 3: rotate, scale, store.
#pragma unroll
    for (int j = 0; j < 8; ++j) {
        const float4 w = sW4[lane + 32 * j];
        float4 o4;
        o4.x = s * (w.x * xv[j].x - w.y * xv[j].y);
        o4.y = s * (w.x * xv[j].y + w.y * xv[j].x);
        o4.z = s * (w.z * xv[j].z - w.w * xv[j].w);
        o4.w = s * (w.z * xv[j].w + w.w * xv[j].z);
        orow[lane + 32 * j] = o4;
    }
}

extern "C" void kernel_launch(void* const* d_in, const int* in_sizes, int n_in,
                              void* d_out, int out_size) {
    const float* x      = (const float*)d_in[0];
    const float* params = (const float*)d_in[1];
    float* out          = (float*)d_out;

    const int rows = in_sizes[0] / DIM;   // 32768
    hyper_butterfly_fused<<<rows >> 3, 256>>>(x, params, out);
}

// round 7
// speedup vs baseline: 1.7854x; 1.7854x over previous
#include <cuda_runtime.h>

#define DIM    1024
#define NPAIRS 512
#define NLAYER 10
#define NPARAMS 4092   // 2 * sum(DIM>>l, l=0..9)

// Composite butterfly coefficients, split by use:
//  g_Wri[k] = (Re W_k, Im W_k)   -> float4 per 2-pair chunk (store pass)
//  g_Wz[k]  = |W_k|^2            -> float2 per 2-pair chunk (norm pass)
__device__ __align__(16) float2 g_Wri[NPAIRS];
__device__ __align__(16) float  g_Wz[NPAIRS];

// The 9 active butterfly layers act on adjacent pair (u0,u1) as [[a,b],[-b,a]],
// i.e. complex multiply by (a - ib). Compose all layers into one W per pair.
//
// KEY FIX vs R4: batch-load ALL params into smem with high MLP first (one DRAM
// round trip), then walk the 9-layer chain from smem (29-cyc LDS, broadcast).
// The R4 version chained 9 dependent cold-DRAM LDGs (~4.7us serial latency).
__global__ void precompute_W_kernel(const float* __restrict__ params) {
    __shared__ float sp[NPARAMS];
    const int t = threadIdx.x;   // 512 threads

    // Coalesced batched load: 8 rounds of 512 threads covers 4096 >= 4092.
#pragma unroll
    for (int j = 0; j < 8; ++j) {
        int i = t + 512 * j;
        if (i < NPARAMS) sp[i] = params[i];
    }
    __syncthreads();

    const int k = t;             // pair index 0..511
    float A = 1.0f, B = 0.0f;
    int off = 2 * DIM;           // layer 0 (bs=1) skipped, consumes 2*1024 params
#pragma unroll
    for (int l = 1; l < NLAYER; ++l) {
        const int blk = k >> (l - 1);
        const float a = sp[off + 2 * blk];
        const float b = sp[off + 2 * blk + 1];
        const float nA = A * a + B * b;   // (A+iB)*(a-ib)
        const float nB = B * a - A * b;
        A = nA; B = nB;
        off += 2 * (DIM >> l);
    }
    g_Wri[k] = make_float2(A, B);
    g_Wz[k]  = A * A + B * B;
}

// Warp-per-row: 8 rows per 256-thread CTA. Each lane owns 8 float4 chunks.
// No shared memory, no __syncthreads — warp-shuffle reduction only; every
// lane computes the scale redundantly. (Identical to the 42.6us R4 kernel.)
__global__ void __launch_bounds__(256)
hyper_butterfly_kernel(const float* __restrict__ x, float* __restrict__ out) {
    const int warp = threadIdx.x >> 5;
    const int lane = threadIdx.x & 31;
    const int row  = (blockIdx.x << 3) + warp;

    const float4* __restrict__ xr = reinterpret_cast<const float4*>(x + (size_t)row * DIM);
    float4* __restrict__ orow     = reinterpret_cast<float4*>(out + (size_t)row * DIM);

    // Front-batched loads of x (MLP=8); ||x||^2 partial needs no W.
    float4 xv[8];
#pragma unroll
    for (int j = 0; j < 8; ++j) xv[j] = xr[lane + 32 * j];

    float r0 = 0.0f;
#pragma unroll
    for (int j = 0; j < 8; ++j)
        r0 += xv[j].x * xv[j].x + xv[j].y * xv[j].y
            + xv[j].z * xv[j].z + xv[j].w * xv[j].w;

    // PDL: wait for precompute_W_kernel's writes before touching W.
    cudaGridDependencySynchronize();

    const float2* __restrict__ wzp = reinterpret_cast<const float2*>(g_Wz);
    float r1 = 0.0f;
#pragma unroll
    for (int j = 0; j < 8; ++j) {
        float2 wz = wzp[lane + 32 * j];
        r1 += wz.x * (xv[j].x * xv[j].x + xv[j].y * xv[j].y)
            + wz.y * (xv[j].z * xv[j].z + xv[j].w * xv[j].w);
    }

    // Warp butterfly reduce both sums; all lanes end with the totals.
#pragma unroll
    for (int o = 16; o; o >>= 1) {
        r0 += __shfl_xor_sync(0xffffffffu, r0, o);
        r1 += __shfl_xor_sync(0xffffffffu, r1, o);
    }

    const float n  = sqrtf(r0);
    const float s1 = atanhf(n) / fmaxf(n, 1e-12f);
    const float m  = s1 * sqrtf(r1);
    const float s  = s1 * tanhf(m) / fmaxf(m, 1e-12f);

    // Apply composite complex rotation per pair, scale, store.
    const float4* __restrict__ wrip = reinterpret_cast<const float4*>(g_Wri);
#pragma unroll
    for (int j = 0; j < 8; ++j) {
        float4 w = wrip[lane + 32 * j];
        float4 o4;
        o4.x = s * (w.x * xv[j].x - w.y * xv[j].y);
        o4.y = s * (w.x * xv[j].y + w.y * xv[j].x);
        o4.z = s * (w.z * xv[j].z - w.w * xv[j].w);
        o4.w = s * (w.z * xv[j].w + w.w * xv[j].z);
        orow[lane + 32 * j] = o4;
    }
}

extern "C" void kernel_launch(void* const* d_in, const int* in_sizes, int n_in,
                              void* d_out, int out_size) {
    const float* x      = (const float*)d_in[0];
    const float* params = (const float*)d_in[1];
    float* out          = (float*)d_out;

    const int rows = in_sizes[0] / DIM;   // 32768

    precompute_W_kernel<<<1, NPAIRS>>>(params);

    // Main kernel with programmatic dependent launch: x-load prologue overlaps
    // the (now short) precompute; cudaGridDependencySynchronize() orders W reads.
    cudaLaunchConfig_t cfg = {};
    cfg.gridDim  = dim3(rows >> 3);
    cfg.blockDim = dim3(256);
    cfg.dynamicSmemBytes = 0;
    cfg.stream = 0;
    cudaLaunchAttribute attr[1];
    attr[0].id = cudaLaunchAttributeProgrammaticStreamSerialization;
    attr[0].val.programmaticStreamSerializationAllowed = 1;
    cfg.attrs = attr;
    cfg.numAttrs = 1;
    cudaLaunchKernelEx(&cfg, hyper_butterfly_kernel, x, out);
}

// round 8
// speedup vs baseline: 1.8072x; 1.0122x over previous
#include <cuda_runtime.h>

#define DIM    1024
#define NPAIRS 512
#define NLAYER 10
#define NPARAMS 4092   // 2 * sum(DIM>>l, l=0..9)

// Composite butterfly coefficients, split by use:
//  g_Wri[k] = (Re W_k, Im W_k)   -> float4 per 2-pair chunk (store pass)
//  g_Wz[k]  = |W_k|^2            -> float2 per 2-pair chunk (norm pass)
__device__ __align__(16) float2 g_Wri[NPAIRS];
__device__ __align__(16) float  g_Wz[NPAIRS];

// The 9 active butterfly layers act on adjacent pair (u0,u1) as [[a,b],[-b,a]],
// i.e. complex multiply by (a - ib). Compose all layers into one W per pair.
// Params are batch-loaded to smem (one coalesced DRAM round trip), then the
// 9-layer chain walks smem.
//
// KEY FIX vs R6: cudaTriggerProgrammaticLaunchCompletion() at the TOP — this
// is what lets the PDL secondary actually launch early. The secondary still
// orders its W reads with cudaGridDependencySynchronize(), which waits for
// this kernel's full completion (so the trigger placement is safe).
__global__ void precompute_W_kernel(const float* __restrict__ params) {
    cudaTriggerProgrammaticLaunchCompletion();

    __shared__ float sp[NPARAMS];
    const int t = threadIdx.x;   // 512 threads

#pragma unroll
    for (int j = 0; j < 8; ++j) {
        int i = t + 512 * j;
        if (i < NPARAMS) sp[i] = params[i];
    }
    __syncthreads();

    const int k = t;             // pair index 0..511
    float A = 1.0f, B = 0.0f;
    int off = 2 * DIM;           // layer 0 (bs=1) skipped, consumes 2*1024 params
#pragma unroll
    for (int l = 1; l < NLAYER; ++l) {
        const int blk = k >> (l - 1);
        const float a = sp[off + 2 * blk];
        const float b = sp[off + 2 * blk + 1];
        const float nA = A * a + B * b;   // (A+iB)*(a-ib)
        const float nB = B * a - A * b;
        A = nA; B = nB;
        off += 2 * (DIM >> l);
    }
    g_Wri[k] = make_float2(A, B);
    g_Wz[k]  = A * A + B * B;
}

// Warp-per-row: 8 rows per 256-thread CTA. Each lane owns 8 float4 chunks.
// No shared memory, no __syncthreads — warp-shuffle reduction only; every
// lane computes the scale redundantly. (Identical to the proven 41.8us kernel.)
__global__ void __launch_bounds__(256)
hyper_butterfly_kernel(const float* __restrict__ x, float* __restrict__ out) {
    const int warp = threadIdx.x >> 5;
    const int lane = threadIdx.x & 31;
    const int row  = (blockIdx.x << 3) + warp;

    const float4* __restrict__ xr = reinterpret_cast<const float4*>(x + (size_t)row * DIM);
    float4* __restrict__ orow     = reinterpret_cast<float4*>(out + (size_t)row * DIM);

    // Front-batched loads of x (MLP=8); ||x||^2 partial needs no W.
    float4 xv[8];
#pragma unroll
    for (int j = 0; j < 8; ++j) xv[j] = xr[lane + 32 * j];

    float r0 = 0.0f;
#pragma unroll
    for (int j = 0; j < 8; ++j)
        r0 += xv[j].x * xv[j].x + xv[j].y * xv[j].y
            + xv[j].z * xv[j].z + xv[j].w * xv[j].w;

    // PDL: wait for precompute_W_kernel's writes before touching W.
    cudaGridDependencySynchronize();

    const float2* __restrict__ wzp = reinterpret_cast<const float2*>(g_Wz);
    float r1 = 0.0f;
#pragma unroll
    for (int j = 0; j < 8; ++j) {
        float2 wz = wzp[lane + 32 * j];
        r1 += wz.x * (xv[j].x * xv[j].x + xv[j].y * xv[j].y)
            + wz.y * (xv[j].z * xv[j].z + xv[j].w * xv[j].w);
    }

    // Warp butterfly reduce both sums; all lanes end with the totals.
#pragma unroll
    for (int o = 16; o; o >>= 1) {
        r0 += __shfl_xor_sync(0xffffffffu, r0, o);
        r1 += __shfl_xor_sync(0xffffffffu, r1, o);
    }

    const float n  = sqrtf(r0);
    const float s1 = atanhf(n) / fmaxf(n, 1e-12f);
    const float m  = s1 * sqrtf(r1);
    const float s  = s1 * tanhf(m) / fmaxf(m, 1e-12f);

    // Apply composite complex rotation per pair, scale, store.
    const float4* __restrict__ wrip = reinterpret_cast<const float4*>(g_Wri);
#pragma unroll
    for (int j = 0; j < 8; ++j) {
        float4 w = wrip[lane + 32 * j];
        float4 o4;
        o4.x = s * (w.x * xv[j].x - w.y * xv[j].y);
        o4.y = s * (w.x * xv[j].y + w.y * xv[j].x);
        o4.z = s * (w.z * xv[j].z - w.w * xv[j].w);
        o4.w = s * (w.z * xv[j].w + w.w * xv[j].z);
        orow[lane + 32 * j] = o4;
    }
}

extern "C" void kernel_launch(void* const* d_in, const int* in_sizes, int n_in,
                              void* d_out, int out_size) {
    const float* x      = (const float*)d_in[0];
    const float* params = (const float*)d_in[1];
    float* out          = (float*)d_out;

    const int rows = in_sizes[0] / DIM;   // 32768

    precompute_W_kernel<<<1, NPAIRS>>>(params);

    // Secondary with programmatic dependent launch: launches while the primary
    // runs (primary triggers at its top); x-load prologue overlaps the W build.
    cudaLaunchConfig_t cfg = {};
    cfg.gridDim  = dim3(rows >> 3);
    cfg.blockDim = dim3(256);
    cfg.dynamicSmemBytes = 0;
    cfg.stream = 0;
    cudaLaunchAttribute attr[1];
    attr[0].id = cudaLaunchAttributeProgrammaticStreamSerialization;
    attr[0].val.programmaticStreamSerializationAllowed = 1;
    cfg.attrs = attr;
    cfg.numAttrs = 1;
    cudaLaunchKernelEx(&cfg, hyper_butterfly_kernel, x, out);
}